// round 17
// baseline (speedup 1.0000x reference)
#include <cuda_runtime.h>
#include <cuda_fp16.h>
#include <cstdint>

// ---------------------------------------------------------------------------
// FNO spectral block, all four DFT stages on fp16 mma.sync tensor cores.
// A: x (B-op) x F(hi+lo) -> A'' fp16 [b][c][2k2ri][h]
// B: E(hi+lo, cos|sin rows) x A'' -> Xp partials (complex combine in-thread)
// C: EC(hi+lo) x BW(complex folded into K) -> Z fp16
// D: GD(hi+lo) x Z -> y   (R14 design, unchanged)
// ---------------------------------------------------------------------------

typedef unsigned long long ull;

// ---- device scratch (allocation-free) ----
__device__ __half g_FBh[64 * 1024], g_FBl[64 * 1024];     // fwd DFT [fcol][w]
__device__ __half g_GDh[1024 * 64], g_GDl[1024 * 64];     // inv DFT [w][fcol]
__device__ __half g_EBth[8 * 128 * 128], g_EBtl[8 * 128 * 128]; // [hq][m][k]
__device__ __half g_ECth[1024 * 128], g_ECtl[1024 * 128]; // [h][2k1i ri]
__device__ float  g_Wc[32 * 64 * 32 * 2];                 // combined weights
__device__ __half g_Af[(size_t)2 * 32 * 64 * 1024];       // A'' [b][c][n][h]
__device__ float  g_Xp[8 * 2 * 32 * 64 * 32 * 2];         // partial X
__device__ __half g_BW[(size_t)2 * 32 * 64 * 128];        // [b][c][2k2ri][2k1ri]
__device__ __half g_Zh[(size_t)2 * 1024 * 32 * 64];       // Z [b][h][c][fcol]

// ---- helpers ----
__device__ __forceinline__ uint32_t smem_u32(const void* p) {
    uint32_t a;
    asm("{ .reg .u64 t; cvta.to.shared.u64 t, %1; cvt.u32.u64 %0, t; }" : "=r"(a) : "l"(p));
    return a;
}
__device__ __forceinline__ void mma_f16(float* d, const uint32_t* a, const uint32_t* b) {
    asm("mma.sync.aligned.m16n8k16.row.col.f32.f16.f16.f32 "
        "{%0,%1,%2,%3}, {%4,%5,%6,%7}, {%8,%9}, {%0,%1,%2,%3};"
        : "+f"(d[0]), "+f"(d[1]), "+f"(d[2]), "+f"(d[3])
        : "r"(a[0]), "r"(a[1]), "r"(a[2]), "r"(a[3]), "r"(b[0]), "r"(b[1]));
}
__device__ __forceinline__ void ldmx4(uint32_t* r, uint32_t addr) {
    asm volatile("ldmatrix.sync.aligned.m8n8.x4.shared.b16 {%0,%1,%2,%3}, [%4];"
                 : "=r"(r[0]), "=r"(r[1]), "=r"(r[2]), "=r"(r[3]) : "r"(addr));
}
__device__ __forceinline__ uint32_t f2h2(float a, float b) {
    __half2 h = __floats2half2_rn(a, b);
    return *(uint32_t*)&h;
}

// ---------------------------------------------------------------------------
// Init: exact mod-1024 phase, sincospif, hi+lo fp16 splits.
// ---------------------------------------------------------------------------
__global__ void k_init_tables() {
    const int row = blockIdx.x;     // w (FB/GD) | h (EBt/ECt)
    const int t = threadIdx.x;      // 0..63
    {
        const int k2 = t >> 1;
        const int r = (k2 * row) & 1023;
        float s, c;
        sincospif((float)r / 512.0f, &s, &c);
        const float vF = (t & 1) ? -s : c;
        const float sc = (k2 == 0 ? 1.0f : 2.0f) / 1024.0f;
        const float vG = (t & 1) ? (-sc * s) : (sc * c);
        const __half fh = __float2half_rn(vF);
        g_FBh[t * 1024 + row] = fh;
        g_FBl[t * 1024 + row] = __float2half_rn(vF - __half2float(fh));
        const __half gh = __float2half_rn(vG);
        g_GDh[row * 64 + t] = gh;
        g_GDl[row * 64 + t] = __float2half_rn(vG - __half2float(gh));
    }
    {
        const int k1i = t;
        const int k1 = (k1i < 32) ? k1i : (960 + k1i);
        const int r = (k1 * row) & 1023;
        float s, c;
        sincospif((float)r / 512.0f, &s, &c);
        const int hq = row >> 7, kk = row & 127;
        const int iC = (hq * 128 + k1i) * 128 + kk;
        const int iS = (hq * 128 + 64 + k1i) * 128 + kk;
        const __half ch = __float2half_rn(c);
        g_EBth[iC] = ch;  g_EBtl[iC] = __float2half_rn(c - __half2float(ch));
        const __half sh = __float2half_rn(s);
        g_EBth[iS] = sh;  g_EBtl[iS] = __float2half_rn(s - __half2float(sh));
        const float ci = c / 1024.0f, si = s / 1024.0f;
        const int iE = row * 128 + 2 * k1i;
        const __half ceh = __float2half_rn(ci);
        g_ECth[iE] = ceh;     g_ECtl[iE] = __float2half_rn(ci - __half2float(ceh));
        const __half seh = __float2half_rn(si);
        g_ECth[iE + 1] = seh; g_ECtl[iE + 1] = __float2half_rn(si - __half2float(seh));
    }
}

__global__ void k_init_w(const float* __restrict__ w0r, const float* __restrict__ w0i,
                         const float* __restrict__ w1r, const float* __restrict__ w1i,
                         const float* __restrict__ w2r, const float* __restrict__ w2i) {
    const int idx = blockIdx.x * 256 + threadIdx.x;   // 65536
    const int k2 = idx & 31;
    const int k1i = (idx >> 5) & 63;
    const int c = idx >> 11;
    const float ar = w0r[c], ai = w0i[c];
    float br, bi;
    if (k1i < 32) { const int o = (c * 32 + k1i) * 32 + k2;        br = w1r[o]; bi = w1i[o]; }
    else          { const int o = (c * 32 + (k1i - 32)) * 32 + k2; br = w2r[o]; bi = w2i[o]; }
    g_Wc[idx * 2]     = ar * br - ai * bi;
    g_Wc[idx * 2 + 1] = ar * bi + ai * br;
}

// ---------------------------------------------------------------------------
// Stage A: CTA per (4h, b).  D[m=fcol 64][n=(4c+hh) 128] = sum_w F[f][w]*x.
// F = A-operand (hi+lo), x = B-operand (swizzled tile).  Out: A'' fp16 [n][h].
// ---------------------------------------------------------------------------
__global__ void __launch_bounds__(128) kTA(const float* __restrict__ x) {
    __shared__ __align__(16) char XS[18432];   // 128 n x 144B (swizzled)
    __shared__ __align__(16) char FH[9216];    // 64 f x 144B
    __shared__ __align__(16) char FL[9216];
    const uint32_t XSb = smem_u32(XS), FHb = smem_u32(FH), FLb = smem_u32(FL);
    const int hg = blockIdx.x, b = blockIdx.y;
    const int t = threadIdx.x, warp = t >> 5, lane = t & 31;
    const int h0 = hg * 4;
    const float* xb = x + (size_t)(b * 1024 + h0) * 32768;
    const int g = lane >> 3, r = lane & 7;
    const int a_m = ((g & 1) << 3) + r, a_k = (g >> 1) << 3;
    const int b_n = ((g >> 1) << 3) + r, b_k = (g & 1) << 3;

    float acc[16][4];
#pragma unroll
    for (int i = 0; i < 16; i++)
#pragma unroll
        for (int q = 0; q < 4; q++) acc[i][q] = 0.f;

    for (int kc = 0; kc < 16; kc++) {
        const int w0 = kc * 64;
        __syncthreads();
        // x: 4h x 64w x 32c -> fp16 XS[n=4c+hh][w], XOR-swizzled 16B granules
#pragma unroll
        for (int j = 0; j < 4; j++) {
            const int idx = t + j * 128;
            const int c4 = idx & 7, wq = (idx >> 3) & 15, hh = idx >> 7;
            const float* p = xb + (size_t)hh * 32768 + (size_t)(w0 + 4 * wq) * 32 + c4 * 4;
            const float4 v0 = *(const float4*)p;
            const float4 v1 = *(const float4*)(p + 32);
            const float4 v2 = *(const float4*)(p + 64);
            const float4 v3 = *(const float4*)(p + 96);
            const float e0[4] = {v0.x, v0.y, v0.z, v0.w};
            const float e1[4] = {v1.x, v1.y, v1.z, v1.w};
            const float e2[4] = {v2.x, v2.y, v2.z, v2.w};
            const float e3[4] = {v3.x, v3.y, v3.z, v3.w};
#pragma unroll
            for (int i = 0; i < 4; i++) {
                const int n = (c4 * 4 + i) * 4 + hh;
                uint2 val;
                val.x = f2h2(e0[i], e1[i]);
                val.y = f2h2(e2[i], e3[i]);
                const int off = n * 144 + (((wq >> 1) ^ ((n >> 4) & 7)) << 4) + ((wq & 1) << 3);
                *(uint2*)(XS + off) = val;
            }
        }
#pragma unroll
        for (int j = 0; j < 4; j++) {
            const int idx = t + j * 128;
            const int f = idx >> 3, q = idx & 7;
            *(uint4*)(FH + f * 144 + q * 16) = *(const uint4*)&g_FBh[f * 1024 + w0 + q * 8];
            *(uint4*)(FL + f * 144 + q * 16) = *(const uint4*)&g_FBl[f * 1024 + w0 + q * 8];
        }
        __syncthreads();
#pragma unroll
        for (int ks = 0; ks < 4; ks++) {
            const int K0 = ks * 16;
            uint32_t fh[4], fl[4];
            const uint32_t ra = (uint32_t)((16 * warp + a_m) * 144 + (K0 + a_k) * 2);
            ldmx4(fh, FHb + ra);
            ldmx4(fl, FLb + ra);
#pragma unroll
            for (int jn = 0; jn < 8; jn++) {
                const int R = jn * 16 + b_n;
                const int g16 = (K0 + b_k) >> 3;
                uint32_t bh[4];
                ldmx4(bh, XSb + (uint32_t)(R * 144 + ((g16 ^ ((R >> 4) & 7)) << 4)));
                mma_f16(acc[2 * jn],     fh, bh);
                mma_f16(acc[2 * jn],     fl, bh);
                mma_f16(acc[2 * jn + 1], fh, bh + 2);
                mma_f16(acc[2 * jn + 1], fl, bh + 2);
            }
        }
    }
    // epilogue: thread holds (f, n0..n0+1) and (f+8, ...)
    const int r0 = lane >> 2, q2 = (lane & 3) * 2;
#pragma unroll
    for (int nt = 0; nt < 16; nt++) {
        const int n0 = 8 * nt + q2;
        const int c = n0 >> 2, hh = n0 & 3;          // hh in {0,2}, pair (hh,hh+1)
        const int f = 16 * warp + r0;
        const size_t base = ((size_t)(b * 32 + c) * 64 + f) * 1024 + h0 + hh;
        *(uint32_t*)&g_Af[base] = f2h2(acc[nt][0], acc[nt][1]);
        *(uint32_t*)&g_Af[base + 8 * 1024] = f2h2(acc[nt][2], acc[nt][3]);
    }
}

// ---------------------------------------------------------------------------
// Stage B (tensor): CTA per (hq, c, b).  M=128 (cos rows | sin rows),
// N=64 (A'' fcol), K=128 h.  Xr = Dc[2k2]+Ds[2k2+1]; Xi = Dc[2k2+1]-Ds[2k2].
// ---------------------------------------------------------------------------
#define SMEM_BT 87040
__global__ void __launch_bounds__(128) kBt() {
    extern __shared__ __align__(16) char sm[];
    char* EH = sm; char* EL = sm + 34816; char* AS = sm + 69632;
    const uint32_t EHb = smem_u32(sm), ELb = EHb + 34816, ASb = EHb + 69632;
    const int hq = blockIdx.x, c = blockIdx.y, b = blockIdx.z;
    const int t = threadIdx.x, warp = t >> 5, lane = t & 31;
    const int g = lane >> 3, r = lane & 7;
    const int a_m = ((g & 1) << 3) + r, a_k = (g >> 1) << 3;
    const int b_n = ((g >> 1) << 3) + r, b_k = (g & 1) << 3;

#pragma unroll
    for (int j = 0; j < 16; j++) {                    // E tiles 128 x 256B
        const int idx = t + j * 128;
        const int row = idx >> 4, q = idx & 15;
        *(uint4*)(EH + row * 272 + q * 16) = *(const uint4*)&g_EBth[(hq * 128 + row) * 128 + q * 8];
        *(uint4*)(EL + row * 272 + q * 16) = *(const uint4*)&g_EBtl[(hq * 128 + row) * 128 + q * 8];
    }
#pragma unroll
    for (int j = 0; j < 8; j++) {                     // A'' tile 64 x 256B
        const int idx = t + j * 128;
        const int row = idx >> 4, q = idx & 15;
        *(uint4*)(AS + row * 272 + q * 16) =
            *(const uint4*)&g_Af[((size_t)(b * 32 + c) * 64 + row) * 1024 + hq * 128 + q * 8];
    }
    __syncthreads();

    float acc[2][8][4];
#pragma unroll
    for (int i = 0; i < 2; i++)
#pragma unroll
        for (int j = 0; j < 8; j++)
#pragma unroll
            for (int q = 0; q < 4; q++) acc[i][j][q] = 0.f;

#pragma unroll
    for (int ks = 0; ks < 8; ks++) {
        const int K0 = ks * 16;
        uint32_t eh[2][4], el[2][4];
#pragma unroll
        for (int t2 = 0; t2 < 2; t2++) {
            const uint32_t ra = (uint32_t)((t2 * 64 + 16 * warp + a_m) * 272 + (K0 + a_k) * 2);
            ldmx4(eh[t2], EHb + ra);
            ldmx4(el[t2], ELb + ra);
        }
#pragma unroll
        for (int jn = 0; jn < 4; jn++) {
            uint32_t bh[4];
            ldmx4(bh, ASb + (uint32_t)((jn * 16 + b_n) * 272 + (K0 + b_k) * 2));
#pragma unroll
            for (int t2 = 0; t2 < 2; t2++) {
                mma_f16(acc[t2][2 * jn],     eh[t2], bh);
                mma_f16(acc[t2][2 * jn],     el[t2], bh);
                mma_f16(acc[t2][2 * jn + 1], eh[t2], bh + 2);
                mma_f16(acc[t2][2 * jn + 1], el[t2], bh + 2);
            }
        }
    }
    const int r0 = lane >> 2, cq = lane & 3;
    const size_t xb = (size_t)(((hq * 2 + b) * 32 + c)) * 64;
#pragma unroll
    for (int j = 0; j < 8; j++) {
        const int k2 = 4 * j + cq;
        const int k1i = 16 * warp + r0;
        float2 v0, v1;
        v0.x = acc[0][j][0] + acc[1][j][1];           // Xr
        v0.y = acc[0][j][1] - acc[1][j][0];           // Xi
        v1.x = acc[0][j][2] + acc[1][j][3];
        v1.y = acc[0][j][3] - acc[1][j][2];
        *(float2*)&g_Xp[((xb + k1i) * 32 + k2) * 2] = v0;
        *(float2*)&g_Xp[((xb + k1i + 8) * 32 + k2) * 2] = v1;
    }
}

// Reduce 8 partials, apply weights, emit complex-folded BW fp16.
__global__ void k_reduce_w() {
    const int id = blockIdx.x * 256 + threadIdx.x;   // 131072
    const int k2 = id & 31, k1i = (id >> 5) & 63, c = (id >> 11) & 31, b = id >> 16;
    float xr = 0.f, xi = 0.f;
#pragma unroll
    for (int hq = 0; hq < 8; hq++) {
        const float2 p = *(const float2*)
            &g_Xp[(size_t)((((hq * 2 + b) * 32 + c) * 64 + k1i) * 32 + k2) * 2];
        xr += p.x; xi += p.y;
    }
    const int wci = ((c << 6) + k1i) * 32 + k2;
    const float wr = g_Wc[wci * 2], wi = g_Wc[wci * 2 + 1];
    const float XWr = xr * wr - xi * wi, XWi = xr * wi + xi * wr;
    const size_t base = ((size_t)(b * 32 + c) * 64 + 2 * k2) * 128 + 2 * k1i;
    *(uint32_t*)&g_BW[base]       = f2h2(XWr, -XWi);
    *(uint32_t*)&g_BW[base + 128] = f2h2(XWi,  XWr);
}

// ---------------------------------------------------------------------------
// Stage C (tensor): CTA per (hc, c, b).  M=128 h, N=64 (Zr|Zi cols),
// K=128 (2k1 x ri folded).  Zr,Zi adjacent cols -> direct f2h2 pack.
// ---------------------------------------------------------------------------
__global__ void __launch_bounds__(128) kCt() {
    extern __shared__ __align__(16) char sm[];
    char* EH = sm; char* EL = sm + 34816; char* BS = sm + 69632;
    const uint32_t EHb = smem_u32(sm), ELb = EHb + 34816, BSb = EHb + 69632;
    const int hc = blockIdx.x, c = blockIdx.y, b = blockIdx.z;
    const int t = threadIdx.x, warp = t >> 5, lane = t & 31;
    const int g = lane >> 3, r = lane & 7;
    const int a_m = ((g & 1) << 3) + r, a_k = (g >> 1) << 3;
    const int b_n = ((g >> 1) << 3) + r, b_k = (g & 1) << 3;

#pragma unroll
    for (int j = 0; j < 16; j++) {
        const int idx = t + j * 128;
        const int row = idx >> 4, q = idx & 15;
        *(uint4*)(EH + row * 272 + q * 16) = *(const uint4*)&g_ECth[(hc * 128 + row) * 128 + q * 8];
        *(uint4*)(EL + row * 272 + q * 16) = *(const uint4*)&g_ECtl[(hc * 128 + row) * 128 + q * 8];
    }
#pragma unroll
    for (int j = 0; j < 8; j++) {
        const int idx = t + j * 128;
        const int row = idx >> 4, q = idx & 15;
        *(uint4*)(BS + row * 272 + q * 16) =
            *(const uint4*)&g_BW[((size_t)(b * 32 + c) * 64 + row) * 128 + q * 8];
    }
    __syncthreads();

    float acc[2][8][4];
#pragma unroll
    for (int i = 0; i < 2; i++)
#pragma unroll
        for (int j = 0; j < 8; j++)
#pragma unroll
            for (int q = 0; q < 4; q++) acc[i][j][q] = 0.f;

#pragma unroll
    for (int ks = 0; ks < 8; ks++) {
        const int K0 = ks * 16;
        uint32_t eh[2][4], el[2][4];
#pragma unroll
        for (int t2 = 0; t2 < 2; t2++) {
            const uint32_t ra = (uint32_t)((t2 * 64 + 16 * warp + a_m) * 272 + (K0 + a_k) * 2);
            ldmx4(eh[t2], EHb + ra);
            ldmx4(el[t2], ELb + ra);
        }
#pragma unroll
        for (int jn = 0; jn < 4; jn++) {
            uint32_t bh[4];
            ldmx4(bh, BSb + (uint32_t)((jn * 16 + b_n) * 272 + (K0 + b_k) * 2));
#pragma unroll
            for (int t2 = 0; t2 < 2; t2++) {
                mma_f16(acc[t2][2 * jn],     eh[t2], bh);
                mma_f16(acc[t2][2 * jn],     el[t2], bh);
                mma_f16(acc[t2][2 * jn + 1], eh[t2], bh + 2);
                mma_f16(acc[t2][2 * jn + 1], el[t2], bh + 2);
            }
        }
    }
    const int r0 = lane >> 2, cq = lane & 3;
#pragma unroll
    for (int t2 = 0; t2 < 2; t2++)
#pragma unroll
        for (int j = 0; j < 8; j++) {
            const int h = hc * 128 + t2 * 64 + 16 * warp + r0;
            const int k2 = 4 * j + cq;
            *(uint32_t*)&g_Zh[(((size_t)b * 1024 + h) * 32 + c) * 64 + 2 * k2] =
                f2h2(acc[t2][j][0], acc[t2][j][1]);
            *(uint32_t*)&g_Zh[(((size_t)b * 1024 + h + 8) * 32 + c) * 64 + 2 * k2] =
                f2h2(acc[t2][j][2], acc[t2][j][3]);
        }
}

// ---------------------------------------------------------------------------
// Stage D (HMMA fp16, R14 design): CTA per (wb=128w, hg=32h, b).
// ---------------------------------------------------------------------------
__global__ void __launch_bounds__(128) kTD(float* __restrict__ y) {
    __shared__ __align__(16) char GH[18432];
    __shared__ __align__(16) char GL[18432];
    __shared__ __align__(16) char ZH[4608];
    const uint32_t GHb = smem_u32(GH), GLb = smem_u32(GL), ZHb = smem_u32(ZH);
    const int wb = blockIdx.x, hg = blockIdx.y, b = blockIdx.z;
    const int t = threadIdx.x, warp = t >> 5, lane = t & 31;
    const int g = lane >> 3, r = lane & 7;
    const int a_m = ((g & 1) << 3) + r, a_k = (g >> 1) << 3;
    const int b_n = ((g >> 1) << 3) + r, b_k = (g & 1) << 3;

#pragma unroll
    for (int j = 0; j < 8; j++) {
        const int idx = t + j * 128;
        const int row = idx >> 3, q = idx & 7;
        *(uint4*)(GH + row * 144 + q * 16) = *(const uint4*)&g_GDh[(wb * 128 + row) * 64 + q * 8];
        *(uint4*)(GL + row * 144 + q * 16) = *(const uint4*)&g_GDl[(wb * 128 + row) * 64 + q * 8];
    }
    __syncthreads();

    const int M0 = warp * 32;
    uint32_t gh[4][2][4], gl[4][2][4];
#pragma unroll
    for (int ks = 0; ks < 4; ks++)
#pragma unroll
        for (int t2 = 0; t2 < 2; t2++) {
            const uint32_t off = (uint32_t)((M0 + 16 * t2 + a_m) * 144 + (ks * 16 + a_k) * 2);
            ldmx4(gh[ks][t2], GHb + off);
            ldmx4(gl[ks][t2], GLb + off);
        }

    const int cq = lane >> 2, f2 = (lane & 3) * 2;
    for (int hh = 0; hh < 32; hh++) {
        const int h = hg * 32 + hh;
        const size_t zb = (size_t)(b * 1024 + h) * 2048;
        __syncthreads();
#pragma unroll
        for (int j = 0; j < 2; j++) {
            const int idx = t + j * 128;
            const int row = idx >> 3, q = idx & 7;
            *(uint4*)(ZH + row * 144 + q * 16) = *(const uint4*)&g_Zh[zb + row * 64 + q * 8];
        }
        __syncthreads();
        float acc[2][4][4];
#pragma unroll
        for (int i = 0; i < 2; i++)
#pragma unroll
            for (int j = 0; j < 4; j++)
#pragma unroll
                for (int q = 0; q < 4; q++) acc[i][j][q] = 0.f;
#pragma unroll
        for (int ks = 0; ks < 4; ks++)
#pragma unroll
            for (int jn = 0; jn < 2; jn++) {
                uint32_t bh[4];
                ldmx4(bh, ZHb + (uint32_t)((jn * 16 + b_n) * 144 + (ks * 16 + b_k) * 2));
#pragma unroll
                for (int t2 = 0; t2 < 2; t2++) {
                    mma_f16(acc[t2][2 * jn],     gh[ks][t2], bh);
                    mma_f16(acc[t2][2 * jn],     gl[ks][t2], bh);
                    mma_f16(acc[t2][2 * jn + 1], gh[ks][t2], bh + 2);
                    mma_f16(acc[t2][2 * jn + 1], gl[ks][t2], bh + 2);
                }
            }
        float* yb = y + (size_t)(b * 1024 + h) * 32768;
#pragma unroll
        for (int t2 = 0; t2 < 2; t2++)
#pragma unroll
            for (int j = 0; j < 4; j++) {
                const int w = wb * 128 + M0 + 16 * t2 + cq;
                const int c = 8 * j + f2;
                *(float2*)&yb[(size_t)w * 32 + c] =
                    make_float2(acc[t2][j][0], acc[t2][j][1]);
                *(float2*)&yb[(size_t)(w + 8) * 32 + c] =
                    make_float2(acc[t2][j][2], acc[t2][j][3]);
            }
    }
}

// ---------------------------------------------------------------------------
extern "C" void kernel_launch(void* const* d_in, const int* in_sizes, int n_in,
                              void* d_out, int out_size) {
    const float* x   = (const float*)d_in[0];
    const float* w0r = (const float*)d_in[1];
    const float* w0i = (const float*)d_in[2];
    const float* w1r = (const float*)d_in[3];
    const float* w1i = (const float*)d_in[4];
    const float* w2r = (const float*)d_in[5];
    const float* w2i = (const float*)d_in[6];
    float* y = (float*)d_out;

    cudaFuncSetAttribute(kBt, cudaFuncAttributeMaxDynamicSharedMemorySize, SMEM_BT);
    cudaFuncSetAttribute(kCt, cudaFuncAttributeMaxDynamicSharedMemorySize, SMEM_BT);

    k_init_tables<<<1024, 64>>>();
    k_init_w<<<256, 256>>>(w0r, w0i, w1r, w1i, w2r, w2i);
    kTA<<<dim3(256, 2), 128>>>(x);
    kBt<<<dim3(8, 32, 2), 128, SMEM_BT>>>();
    k_reduce_w<<<512, 256>>>();
    kCt<<<dim3(8, 32, 2), 128, SMEM_BT>>>();
    kTD<<<dim3(8, 32, 2), 128>>>(y);
}